// round 10
// baseline (speedup 1.0000x reference)
#include <cuda_runtime.h>
#include <cuda_bf16.h>
#include <math.h>
#include <cstdint>

// ---------------- Problem constants ----------------
constexpr int B   = 2;
constexpr int S   = 2048;
constexpr int D   = 2560;
constexpr int H   = 8;
constexpr int HKV = 4;
constexpr int HD  = 256;
constexpr int NTOK = B * S;                 // 4096
constexpr int QKV_COLS = H*HD + 2*HKV*HD;   // 4096
constexpr float EPS = 1e-6f;
constexpr float SCALING = 0.0625f;
constexpr float SOFTCAP = 4096.0f;
constexpr float NEGBIG = -1e9f;

constexpr int K1 = D;          // 2560
constexpr int K1C = 3 * K1;    // 7680
constexpr int K2 = H * HD;     // 2048
constexpr int K2C = 3 * K2;    // 6144

// ---------------- Scratch (device globals) ----------------
__device__ float g_qkv[(size_t)NTOK * QKV_COLS];
__device__ __nv_bfloat16 g_xcat  [(size_t)NTOK * K1C];
__device__ __nv_bfloat16 g_wqkvc [(size_t)QKV_COLS * K1C];
__device__ __nv_bfloat16 g_acat  [(size_t)NTOK * K2C];
__device__ __nv_bfloat16 g_woc   [(size_t)D * K2C];
__device__ __nv_bfloat16 g_qh[(size_t)B * H   * S * HD];
__device__ __nv_bfloat16 g_ql[(size_t)B * H   * S * HD];
__device__ __nv_bfloat16 g_kh[(size_t)B * HKV * S * HD];
__device__ __nv_bfloat16 g_kl[(size_t)B * HKV * S * HD];
__device__ __nv_bfloat16 g_vh[(size_t)B * HKV * S * HD];
__device__ __nv_bfloat16 g_vl[(size_t)B * HKV * S * HD];

// ================= helpers =================
__device__ __forceinline__ uint32_t smem_to_u32(const void* p) {
    uint32_t a;
    asm("{ .reg .u64 t; cvta.to.shared.u64 t, %1; cvt.u32.u64 %0, t; }" : "=r"(a) : "l"(p));
    return a;
}
#define SWZ128(o) ((o) ^ (((o) >> 3) & 0x70))

__device__ __forceinline__ void cp16(uint32_t s, const void* g) {
    asm volatile("cp.async.cg.shared.global [%0], [%1], 16;\n" :: "r"(s), "l"(g));
}
#define CP_COMMIT() asm volatile("cp.async.commit_group;\n" ::: "memory")
template<int N> __device__ __forceinline__ void cp_wait() {
    asm volatile("cp.async.wait_group %0;\n" :: "n"(N) : "memory");
}

__device__ __forceinline__ void ldm_x4(uint32_t* r, uint32_t addr) {
    asm volatile("ldmatrix.sync.aligned.m8n8.x4.shared.b16 {%0,%1,%2,%3}, [%4];"
        : "=r"(r[0]), "=r"(r[1]), "=r"(r[2]), "=r"(r[3]) : "r"(addr));
}
__device__ __forceinline__ void ldm_x4_t(uint32_t* r, uint32_t addr) {
    asm volatile("ldmatrix.sync.aligned.m8n8.x4.trans.shared.b16 {%0,%1,%2,%3}, [%4];"
        : "=r"(r[0]), "=r"(r[1]), "=r"(r[2]), "=r"(r[3]) : "r"(addr));
}
__device__ __forceinline__ void mma_bf16(float* d, const uint32_t* a, uint32_t b0, uint32_t b1) {
    asm volatile("mma.sync.aligned.m16n8k16.row.col.f32.bf16.bf16.f32 "
        "{%0,%1,%2,%3}, {%4,%5,%6,%7}, {%8,%9}, {%0,%1,%2,%3};"
        : "+f"(d[0]), "+f"(d[1]), "+f"(d[2]), "+f"(d[3])
        : "r"(a[0]), "r"(a[1]), "r"(a[2]), "r"(a[3]), "r"(b0), "r"(b1));
}
__device__ __forceinline__ uint32_t pack_bf16(float a, float b) {
    __nv_bfloat162 t = __floats2bfloat162_rn(a, b);
    return *(uint32_t*)&t;
}

// ================ Split-precision conversion kernels ================
__device__ __forceinline__ void split4(float4 v, __nv_bfloat16* h, __nv_bfloat16* l) {
    h[0] = __float2bfloat16(v.x); l[0] = __float2bfloat16(v.x - __bfloat162float(h[0]));
    h[1] = __float2bfloat16(v.y); l[1] = __float2bfloat16(v.y - __bfloat162float(h[1]));
    h[2] = __float2bfloat16(v.z); l[2] = __float2bfloat16(v.z - __bfloat162float(h[2]));
    h[3] = __float2bfloat16(v.w); l[3] = __float2bfloat16(v.w - __bfloat162float(h[3]));
}
__device__ __forceinline__ void st8(__nv_bfloat16* p, const __nv_bfloat16* v) {
    *(uint2*)p = *(const uint2*)v;
}

__global__ __launch_bounds__(256) void conv_cat(const float* __restrict__ src,
                                                __nv_bfloat16* __restrict__ dst,
                                                int K, long tot, int mode)
{
    long idx = (long)blockIdx.x * 256 + threadIdx.x;
    if (idx >= tot) return;
    int kq = K >> 2;
    long r = idx / kq; int k4 = (int)(idx - r * kq);
    float4 v = ((const float4*)src)[idx];
    __nv_bfloat16 h[4], l[4];
    split4(v, h, l);
    __nv_bfloat16* row = dst + r * (long)(3 * K);
    st8(row + k4 * 4, h);
    st8(row + K + k4 * 4, mode ? h : l);
    st8(row + 2 * K + k4 * 4, mode ? l : h);
}

__global__ __launch_bounds__(256) void conv_cat_qkv(const float* __restrict__ qw,
                                                    const float* __restrict__ kw,
                                                    const float* __restrict__ vw,
                                                    __nv_bfloat16* __restrict__ dst)
{
    const int K = K1, kq = K >> 2;
    long idx = (long)blockIdx.x * 256 + threadIdx.x;
    long tot = (long)QKV_COLS * kq;
    if (idx >= tot) return;
    long r = idx / kq; int k4 = (int)(idx - r * kq);
    const float* src = (r < 2048) ? qw + r * (long)K
                     : (r < 3072) ? kw + (r - 2048) * (long)K
                                  : vw + (r - 3072) * (long)K;
    float4 v = ((const float4*)src)[k4];
    __nv_bfloat16 h[4], l[4];
    split4(v, h, l);
    __nv_bfloat16* row = dst + r * (long)(3 * K);
    st8(row + k4 * 4, h);
    st8(row + K + k4 * 4, h);
    st8(row + 2 * K + k4 * 4, l);
}

// ================ bf16 HMMA GEMM (unchanged) ================
constexpr int STAGE_BYTES = 32768;
constexpr int NSTAGE = 3;
constexpr int GEMM_SMEM = NSTAGE * STAGE_BYTES;

__device__ __forceinline__ void load_chunk(const char* Arow, const char* Brow, size_t rowbytes,
                                           uint32_t smem_base, int stage, long kbyte, int tid)
{
    uint32_t sa = smem_base + stage * STAGE_BYTES;
    uint32_t sb = sa + 16384;
#pragma unroll
    for (int p = 0; p < 4; p++) {
        int idx = p * 256 + tid;
        int row = idx >> 3, j = idx & 7;
        uint32_t off = (uint32_t)(row * 128 + j * 16);
        cp16(sa + SWZ128(off), Arow + (size_t)row * rowbytes + kbyte + j * 16);
    }
#pragma unroll
    for (int p = 0; p < 4; p++) {
        int idx = p * 256 + tid;
        int row = idx >> 3, j = idx & 7;
        uint32_t off = (uint32_t)(row * 128 + j * 16);
        cp16(sb + SWZ128(off), Brow + (size_t)row * rowbytes + kbyte + j * 16);
    }
    CP_COMMIT();
}

__global__ __launch_bounds__(256) void gemm_bf16(const __nv_bfloat16* __restrict__ A,
                                                 const __nv_bfloat16* __restrict__ Bw,
                                                 float* __restrict__ C,
                                                 int Kp, int Ntot)
{
    extern __shared__ char smem[];
    const uint32_t smem_base = smem_to_u32(smem);
    const int tid = threadIdx.x;
    const int wid = tid >> 5, lane = tid & 31;
    const int wm = wid & 1;
    const int wn = wid >> 1;
    const int n0 = blockIdx.x * 128;
    const int m0 = blockIdx.y * 128;

    const size_t rowbytes = (size_t)Kp * 2;
    const char* Arow = (const char*)A + (size_t)m0 * rowbytes;
    const char* Brow = (const char*)Bw + (size_t)n0 * rowbytes;
    const int C_chunks = Kp / 64;

    load_chunk(Arow, Brow, rowbytes, smem_base, 0, 0, tid);
    load_chunk(Arow, Brow, rowbytes, smem_base, 1, 128, tid);
    load_chunk(Arow, Brow, rowbytes, smem_base, 2, 256, tid);

    float acc[4][4][4];
#pragma unroll
    for (int i = 0; i < 4; i++)
#pragma unroll
        for (int j = 0; j < 4; j++)
#pragma unroll
            for (int q = 0; q < 4; q++) acc[i][j][q] = 0.f;

    const int a_row_l = (lane & 15);
    const int a_hi    = (lane >> 4) * 16;
    const int b_row_l = (lane & 7) + ((lane >> 4) & 1) * 8;
    const int b_hi    = ((lane >> 3) & 1) * 16;

    for (int c = 0; c < C_chunks; c++) {
        const int s = c % 3;
        if (c + 2 < C_chunks)      cp_wait<2>();
        else if (c + 1 < C_chunks) cp_wait<1>();
        else                       cp_wait<0>();
        __syncthreads();

        const uint32_t sa = smem_base + s * STAGE_BYTES;
        const uint32_t sb = sa + 16384;

#pragma unroll
        for (int ks = 0; ks < 4; ks++) {
            uint32_t a[4][4];
#pragma unroll
            for (int mf = 0; mf < 4; mf++) {
                int row = wm * 64 + mf * 16 + a_row_l;
                uint32_t kb = (uint32_t)(ks * 32 + a_hi) ^ ((uint32_t)(row & 7) << 4);
                ldm_x4(a[mf], sa + row * 128 + kb);
            }
            uint32_t bfr[2][4];
#pragma unroll
            for (int nb = 0; nb < 2; nb++) {
                int row = wn * 32 + nb * 16 + b_row_l;
                uint32_t kb = (uint32_t)(ks * 32 + b_hi) ^ ((uint32_t)(row & 7) << 4);
                ldm_x4(bfr[nb], sb + row * 128 + kb);
            }
#pragma unroll
            for (int mf = 0; mf < 4; mf++) {
#pragma unroll
                for (int nf = 0; nf < 4; nf++)
                    mma_bf16(acc[mf][nf], a[mf], bfr[nf >> 1][(nf & 1) * 2], bfr[nf >> 1][(nf & 1) * 2 + 1]);
            }
        }
        __syncthreads();
        if (c + 3 < C_chunks)
            load_chunk(Arow, Brow, rowbytes, smem_base, s, (long)(c + 3) * 128, tid);
    }

    const int er = lane >> 2;
    const int ec = (lane & 3) * 2;
#pragma unroll
    for (int mf = 0; mf < 4; mf++) {
        const int rbase = m0 + wm * 64 + mf * 16 + er;
#pragma unroll
        for (int nf = 0; nf < 4; nf++) {
            const int cbase = n0 + wn * 32 + nf * 8 + ec;
            float* p0 = C + (size_t)rbase * Ntot + cbase;
            float* p1 = C + (size_t)(rbase + 8) * Ntot + cbase;
            *(float2*)p0 = make_float2(acc[mf][nf][0], acc[mf][nf][1]);
            *(float2*)p1 = make_float2(acc[mf][nf][2], acc[mf][nf][3]);
        }
    }
}

// ---------------- RMSNorm + RoPE -> bf16 hi/lo split (unchanged) ----------------
__global__ __launch_bounds__(256) void norm_rope_kernel(
    const float* __restrict__ cosp, const float* __restrict__ sinp,
    const float* __restrict__ qn_w, const float* __restrict__ kn_w)
{
    const int token = blockIdx.x;
    const int slot  = blockIdx.y;
    const int d     = threadIdx.x;
    const int b = token / S;
    const int s = token % S;

    const float* row = g_qkv + (size_t)token * QKV_COLS;
    float x;
    if (slot < 8)       x = row[slot * HD + d];
    else if (slot < 12) x = row[2048 + (slot - 8) * HD + d];
    else                x = row[3072 + (slot - 12) * HD + d];

    if (slot >= 12) {
        size_t o = (((size_t)b * HKV + (slot - 12)) * S + s) * HD + d;
        __nv_bfloat16 hb = __float2bfloat16(x);
        g_vh[o] = hb;
        g_vl[o] = __float2bfloat16(x - __bfloat162float(hb));
        return;
    }

    __shared__ float red[8];
    __shared__ float xs[HD];
    float ss = x * x;
#pragma unroll
    for (int o = 16; o > 0; o >>= 1) ss += __shfl_xor_sync(0xffffffffu, ss, o);
    if ((d & 31) == 0) red[d >> 5] = ss;
    __syncthreads();
    float tot = red[0];
#pragma unroll
    for (int i = 1; i < 8; i++) tot += red[i];
    const float scale = rsqrtf(tot * (1.0f / HD) + EPS);

    const float* nw = (slot < 8) ? qn_w : kn_w;
    const float xn = x * scale * (1.0f + nw[d]);
    xs[d] = xn;
    __syncthreads();

    const float rot = (d < HD/2) ? -xs[d + HD/2] : xs[d - HD/2];
    const size_t csi = ((size_t)b * S + s) * HD + d;
    const float out = xn * cosp[csi] + rot * sinp[csi];

    __nv_bfloat16 hb = __float2bfloat16(out);
    __nv_bfloat16 lb = __float2bfloat16(out - __bfloat162float(hb));
    if (slot < 8) {
        size_t o = (((size_t)b * H + slot) * S + s) * HD + d;
        g_qh[o] = hb; g_ql[o] = lb;
    } else {
        size_t o = (((size_t)b * HKV + (slot - 8)) * S + s) * HD + d;
        g_kh[o] = hb; g_kl[o] = lb;
    }
}

// ---------------- Flash attention v3: GQA-fused, 8 warps, BN=16, 2-stage ----------------
// CTA: 64 q-rows x 2 q-heads sharing one kv head. 256 threads.
// smem: Qh[2][64][512B] (64KB) | Ql[2][64][512B] (64KB) | 2 stages x {Kh,Kl,Vh,Vl}[16][512B] (2x32KB).
constexpr int FLASH3_SMEM = 196608;
constexpr uint32_t KV_OFF = 131072;

__device__ __forceinline__ void flash_load_kv(
    const __nv_bfloat16* Khp, const __nv_bfloat16* Klp,
    const __nv_bfloat16* Vhp, const __nv_bfloat16* Vlp,
    uint32_t sb0, int buf, int j0, int tid)
{
    uint32_t sB = sb0 + KV_OFF + (uint32_t)buf * 32768;
#pragma unroll
    for (int p = 0; p < 2; p++) {
        int u = p * 256 + tid;
        int row = u >> 5, c = u & 31;
        uint32_t off = (uint32_t)row * 512 + (((uint32_t)c * 16) ^ (((uint32_t)row & 7) << 4));
        size_t g = (size_t)(j0 + row) * HD + c * 8;
        cp16(sB + off,         Khp + g);
        cp16(sB + 8192 + off,  Klp + g);
        cp16(sB + 16384 + off, Vhp + g);
        cp16(sB + 24576 + off, Vlp + g);
    }
    CP_COMMIT();
}

__global__ __launch_bounds__(256, 1) void flash_mma()
{
    extern __shared__ char fsm[];
    const uint32_t sb0 = smem_to_u32(fsm);

    const int qt = blockIdx.x;        // 0..31, 64 q rows
    const int hk = blockIdx.y;        // kv head
    const int b  = blockIdx.z;
    const int q0 = qt * 64;

    const int tid = threadIdx.x, warp = tid >> 5, lane = tid & 31;
    const int head = warp >> 2;       // 0..1 -> q head 2*hk+head
    const int wq   = warp & 3;        // 16-row group
    const int hq   = 2 * hk + head;

    const __nv_bfloat16* Khp = g_kh + (((size_t)b * HKV + hk) * S) * HD;
    const __nv_bfloat16* Klp = g_kl + (((size_t)b * HKV + hk) * S) * HD;
    const __nv_bfloat16* Vhp = g_vh + (((size_t)b * HKV + hk) * S) * HD;
    const __nv_bfloat16* Vlp = g_vl + (((size_t)b * HKV + hk) * S) * HD;

    // Q load: 2 heads x 64 rows x 32 16B-chunks, hi+lo
    for (int u = tid; u < 4096; u += 256) {
        int hd2 = u >> 11;
        int row = (u >> 5) & 63;
        int c   = u & 31;
        uint32_t off = (uint32_t)hd2 * 32768 + (uint32_t)row * 512
                     + (((uint32_t)c * 16) ^ (((uint32_t)row & 7) << 4));
        size_t g = (((size_t)b * H + 2 * hk + hd2) * S + q0 + row) * HD + c * 8;
        cp16(sb0 + off,         g_qh + g);
        cp16(sb0 + 65536 + off, g_ql + g);
    }
    CP_COMMIT();

    const int ntiles = 4 * (qt + 1);
    flash_load_kv(Khp, Klp, Vhp, Vlp, sb0, 0, 0, tid);
    flash_load_kv(Khp, Klp, Vhp, Vlp, sb0, 1, 16, tid);

    float acc[32][4];
#pragma unroll
    for (int i = 0; i < 32; i++) { acc[i][0]=0.f; acc[i][1]=0.f; acc[i][2]=0.f; acc[i][3]=0.f; }
    float mrow0 = -1e30f, mrow1 = -1e30f, lrow0 = 0.f, lrow1 = 0.f;

    const int rA = q0 + wq * 16 + (lane >> 2);

    const uint32_t sQh = sb0 + (uint32_t)head * 32768;
    const uint32_t sQl = sb0 + 65536 + (uint32_t)head * 32768;
    const int arow = wq * 16 + (lane & 15);
    const uint32_t aswz = ((uint32_t)(arow & 7)) << 4;
    const uint32_t asel = (uint32_t)(lane >> 4) * 16;
    const int brow = (lane & 7) + ((lane >> 4) & 1) * 8;
    const uint32_t bswz = ((uint32_t)(brow & 7)) << 4;
    const uint32_t bsel = (uint32_t)((lane >> 3) & 1) * 16;
    const int vrow_l = (lane & 7) + ((lane >> 3) & 1) * 8;
    const uint32_t vswz = ((uint32_t)(vrow_l & 7)) << 4;
    const uint32_t vdsel = (uint32_t)((lane >> 4) & 1) * 16;

    for (int t = 0; t < ntiles; t++) {
        if (t + 1 < ntiles) cp_wait<1>(); else cp_wait<0>();
        __syncthreads();
        const uint32_t sK = sb0 + KV_OFF + (uint32_t)(t & 1) * 32768;
        const uint32_t sVh = sK + 16384;
        const uint32_t sVl = sK + 24576;

        // ---- QK^T: m16 x n16, K=256, 3 split terms ----
        float sc[2][4];
        sc[0][0]=0.f; sc[0][1]=0.f; sc[0][2]=0.f; sc[0][3]=0.f;
        sc[1][0]=0.f; sc[1][1]=0.f; sc[1][2]=0.f; sc[1][3]=0.f;

#pragma unroll 4
        for (int kc = 0; kc < 16; kc++) {
            uint32_t kb_a = ((uint32_t)(kc * 32) + asel) ^ aswz;
            uint32_t aq[4], al[4];
            ldm_x4(aq, sQh + (uint32_t)arow * 512 + kb_a);
            ldm_x4(al, sQl + (uint32_t)arow * 512 + kb_a);
            uint32_t kb_b = ((uint32_t)(kc * 32) + bsel) ^ bswz;
            uint32_t bh[4], bl[4];
            ldm_x4(bh, sK + (uint32_t)brow * 512 + kb_b);
            ldm_x4(bl, sK + 8192 + (uint32_t)brow * 512 + kb_b);

            mma_bf16(sc[0], aq, bh[0], bh[1]); mma_bf16(sc[0], al, bh[0], bh[1]); mma_bf16(sc[0], aq, bl[0], bl[1]);
            mma_bf16(sc[1], aq, bh[2], bh[3]); mma_bf16(sc[1], al, bh[2], bh[3]); mma_bf16(sc[1], aq, bl[2], bl[3]);
        }

        // ---- polynomial softcap + causal mask + online softmax ----
        const int j0 = t * 16;
        float mn0 = mrow0, mn1 = mrow1;
#pragma unroll
        for (int nf = 0; nf < 2; nf++) {
            const int cb = j0 + nf * 8 + (lane & 3) * 2;
#pragma unroll
            for (int e = 0; e < 4; e++) {
                float w = sc[nf][e] * SCALING;
                const float tt = w * (1.0f / SOFTCAP);
                w = w * (1.0f - 0.33333333f * tt * tt);   // C*tanh(w/C), |tt|<=0.004
                const int col = cb + (e & 1);
                const int rowg = (e < 2) ? rA : (rA + 8);
                if (col > rowg) w = NEGBIG;
                sc[nf][e] = w;
                if (e < 2) mn0 = fmaxf(mn0, w); else mn1 = fmaxf(mn1, w);
            }
        }
        mn0 = fmaxf(mn0, __shfl_xor_sync(0xffffffffu, mn0, 1));
        mn0 = fmaxf(mn0, __shfl_xor_sync(0xffffffffu, mn0, 2));
        mn1 = fmaxf(mn1, __shfl_xor_sync(0xffffffffu, mn1, 1));
        mn1 = fmaxf(mn1, __shfl_xor_sync(0xffffffffu, mn1, 2));
        const float corr0 = __expf(mrow0 - mn0);
        const float corr1 = __expf(mrow1 - mn1);
        mrow0 = mn0; mrow1 = mn1;

        float ps0 = 0.f, ps1 = 0.f;
        uint32_t aph[4], apl[4];
#pragma unroll
        for (int hf = 0; hf < 2; hf++) {
            float p00 = __expf(sc[hf][0] - mn0), p01 = __expf(sc[hf][1] - mn0);
            float p10 = __expf(sc[hf][2] - mn1), p11 = __expf(sc[hf][3] - mn1);
            ps0 += p00 + p01; ps1 += p10 + p11;
            float h00 = __bfloat162float(__float2bfloat16(p00));
            float h01 = __bfloat162float(__float2bfloat16(p01));
            float h10 = __bfloat162float(__float2bfloat16(p10));
            float h11 = __bfloat162float(__float2bfloat16(p11));
            aph[hf * 2 + 0] = pack_bf16(h00, h01);
            aph[hf * 2 + 1] = pack_bf16(h10, h11);
            apl[hf * 2 + 0] = pack_bf16(p00 - h00, p01 - h01);
            apl[hf * 2 + 1] = pack_bf16(p10 - h10, p11 - h11);
        }
        ps0 += __shfl_xor_sync(0xffffffffu, ps0, 1);
        ps0 += __shfl_xor_sync(0xffffffffu, ps0, 2);
        ps1 += __shfl_xor_sync(0xffffffffu, ps1, 1);
        ps1 += __shfl_xor_sync(0xffffffffu, ps1, 2);
        lrow0 = lrow0 * corr0 + ps0;
        lrow1 = lrow1 * corr1 + ps1;

#pragma unroll
        for (int nf = 0; nf < 32; nf++) {
            acc[nf][0] *= corr0; acc[nf][1] *= corr0;
            acc[nf][2] *= corr1; acc[nf][3] *= corr1;
        }

        // ---- PV: A = p frags, B = V via trans ldmatrix; 3 split terms ----
        const uint32_t vbh = sVh + (uint32_t)vrow_l * 512;
        const uint32_t vbl = sVl + (uint32_t)vrow_l * 512;
#pragma unroll
        for (int g16 = 0; g16 < 16; g16++) {
            uint32_t dby = ((uint32_t)(g16 * 32) + vdsel) ^ vswz;
            uint32_t vh[4], vl[4];
            ldm_x4_t(vh, vbh + dby);
            ldm_x4_t(vl, vbl + dby);
            mma_bf16(acc[2 * g16],     aph, vh[0], vh[1]);
            mma_bf16(acc[2 * g16],     apl, vh[0], vh[1]);
            mma_bf16(acc[2 * g16],     aph, vl[0], vl[1]);
            mma_bf16(acc[2 * g16 + 1], aph, vh[2], vh[3]);
            mma_bf16(acc[2 * g16 + 1], apl, vh[2], vh[3]);
            mma_bf16(acc[2 * g16 + 1], aph, vl[2], vl[3]);
        }

        __syncthreads();
        if (t + 2 < ntiles)
            flash_load_kv(Khp, Klp, Vhp, Vlp, sb0, t & 1, (t + 2) * 16, tid);
    }

    // ---- epilogue: normalize + split-write into g_acat [hi|lo|hi] ----
    const float inv0 = 1.0f / lrow0;
    const float inv1 = 1.0f / lrow1;
    const size_t tokA = (size_t)b * S + q0 + wq * 16 + (lane >> 2);
    __nv_bfloat16* rowA = g_acat + tokA * (size_t)K2C + hq * HD;
    __nv_bfloat16* rowB = g_acat + (tokA + 8) * (size_t)K2C + hq * HD;
#pragma unroll
    for (int nf = 0; nf < 32; nf++) {
        const int d = nf * 8 + (lane & 3) * 2;
        {
            float v0 = acc[nf][0] * inv0, v1 = acc[nf][1] * inv0;
            float h0 = __bfloat162float(__float2bfloat16(v0));
            float h1 = __bfloat162float(__float2bfloat16(v1));
            __nv_bfloat162 hp = __floats2bfloat162_rn(h0, h1);
            __nv_bfloat162 lp = __floats2bfloat162_rn(v0 - h0, v1 - h1);
            *(__nv_bfloat162*)(rowA + d)          = hp;
            *(__nv_bfloat162*)(rowA + K2 + d)     = lp;
            *(__nv_bfloat162*)(rowA + 2 * K2 + d) = hp;
        }
        {
            float v0 = acc[nf][2] * inv1, v1 = acc[nf][3] * inv1;
            float h0 = __bfloat162float(__float2bfloat16(v0));
            float h1 = __bfloat162float(__float2bfloat16(v1));
            __nv_bfloat162 hp = __floats2bfloat162_rn(h0, h1);
            __nv_bfloat162 lp = __floats2bfloat162_rn(v0 - h0, v1 - h1);
            *(__nv_bfloat162*)(rowB + d)          = hp;
            *(__nv_bfloat162*)(rowB + K2 + d)     = lp;
            *(__nv_bfloat162*)(rowB + 2 * K2 + d) = hp;
        }
    }
}

// ---------------- Host launch ----------------
extern "C" void kernel_launch(void* const* d_in, const int* in_sizes, int n_in,
                              void* d_out, int out_size)
{
    const float* x    = (const float*)d_in[0];
    const float* cosp = (const float*)d_in[1];
    const float* sinp = (const float*)d_in[2];
    const float* q_w  = (const float*)d_in[4];
    const float* k_w  = (const float*)d_in[5];
    const float* v_w  = (const float*)d_in[6];
    const float* o_w  = (const float*)d_in[7];
    const float* qn_w = (const float*)d_in[8];
    const float* kn_w = (const float*)d_in[9];
    float* out = (float*)d_out;

    void *p_qkv, *p_xcat, *p_wqkvc, *p_acat, *p_woc;
    cudaGetSymbolAddress(&p_qkv,   g_qkv);
    cudaGetSymbolAddress(&p_xcat,  g_xcat);
    cudaGetSymbolAddress(&p_wqkvc, g_wqkvc);
    cudaGetSymbolAddress(&p_acat,  g_acat);
    cudaGetSymbolAddress(&p_woc,   g_woc);
    float* qkv = (float*)p_qkv;
    __nv_bfloat16* xcat  = (__nv_bfloat16*)p_xcat;
    __nv_bfloat16* wqkvc = (__nv_bfloat16*)p_wqkvc;
    __nv_bfloat16* acat  = (__nv_bfloat16*)p_acat;
    __nv_bfloat16* woc   = (__nv_bfloat16*)p_woc;

    cudaFuncSetAttribute(gemm_bf16, cudaFuncAttributeMaxDynamicSharedMemorySize, GEMM_SMEM);
    cudaFuncSetAttribute(flash_mma, cudaFuncAttributeMaxDynamicSharedMemorySize, FLASH3_SMEM);

    // 1) split-convert x and QKV weights
    {
        long tot = (long)NTOK * (K1 / 4);
        conv_cat<<<(unsigned)((tot + 255) / 256), 256>>>(x, xcat, K1, tot, 0);
        long totw = (long)QKV_COLS * (K1 / 4);
        conv_cat_qkv<<<(unsigned)((totw + 255) / 256), 256>>>(q_w, k_w, v_w, wqkvc);
    }
    // 2) QKV projection (bf16x3 HMMA)
    gemm_bf16<<<dim3(QKV_COLS / 128, NTOK / 128), 256, GEMM_SMEM>>>(xcat, wqkvc, qkv, K1C, QKV_COLS);

    // 3) RMSNorm + RoPE + bf16 hi/lo split
    norm_rope_kernel<<<dim3(NTOK, 16), 256>>>(cosp, sinp, qn_w, kn_w);

    // 4) Flash attention v3 (GQA-fused, 8 warps, double-buffered)
    flash_mma<<<dim3(S / 64, HKV, B), 256, FLASH3_SMEM>>>();

    // 5) split-convert O weights
    {
        long totw = (long)D * (K2 / 4);
        conv_cat<<<(unsigned)((totw + 255) / 256), 256>>>(o_w, woc, K2, totw, 1);
    }
    // 6) O projection
    gemm_bf16<<<dim3(D / 128, NTOK / 128), 256, GEMM_SMEM>>>(acat, woc, out, K2C, D);
}

// round 11
// speedup vs baseline: 1.0796x; 1.0796x over previous
#include <cuda_runtime.h>
#include <cuda_bf16.h>
#include <math.h>
#include <cstdint>

// ---------------- Problem constants ----------------
constexpr int B   = 2;
constexpr int S   = 2048;
constexpr int D   = 2560;
constexpr int H   = 8;
constexpr int HKV = 4;
constexpr int HD  = 256;
constexpr int NTOK = B * S;                 // 4096
constexpr int QKV_COLS = H*HD + 2*HKV*HD;   // 4096
constexpr float EPS = 1e-6f;
constexpr float SCALING = 0.0625f;
constexpr float SOFTCAP = 4096.0f;
constexpr float NEGBIG = -1e9f;

constexpr int K1 = D;          // 2560
constexpr int K2 = H * HD;     // 2048

// ---------------- Scratch (device globals) ----------------
__device__ float g_qkv[(size_t)NTOK * QKV_COLS];
// hi/lo split operands
__device__ __nv_bfloat16 g_xh [(size_t)NTOK * K1];
__device__ __nv_bfloat16 g_xl [(size_t)NTOK * K1];
__device__ __nv_bfloat16 g_wh [(size_t)QKV_COLS * K1];
__device__ __nv_bfloat16 g_wl [(size_t)QKV_COLS * K1];
__device__ __nv_bfloat16 g_ah [(size_t)NTOK * K2];
__device__ __nv_bfloat16 g_al [(size_t)NTOK * K2];
__device__ __nv_bfloat16 g_owh[(size_t)D * K2];
__device__ __nv_bfloat16 g_owl[(size_t)D * K2];
// split q/k/v for HMMA flash
__device__ __nv_bfloat16 g_qh[(size_t)B * H   * S * HD];
__device__ __nv_bfloat16 g_ql[(size_t)B * H   * S * HD];
__device__ __nv_bfloat16 g_kh[(size_t)B * HKV * S * HD];
__device__ __nv_bfloat16 g_kl[(size_t)B * HKV * S * HD];
__device__ __nv_bfloat16 g_vh[(size_t)B * HKV * S * HD];
__device__ __nv_bfloat16 g_vl[(size_t)B * HKV * S * HD];

// ================= helpers =================
__device__ __forceinline__ uint32_t smem_to_u32(const void* p) {
    uint32_t a;
    asm("{ .reg .u64 t; cvta.to.shared.u64 t, %1; cvt.u32.u64 %0, t; }" : "=r"(a) : "l"(p));
    return a;
}
#define SWZ128(o) ((o) ^ (((o) >> 3) & 0x70))

__device__ __forceinline__ void cp16(uint32_t s, const void* g) {
    asm volatile("cp.async.cg.shared.global [%0], [%1], 16;\n" :: "r"(s), "l"(g));
}
#define CP_COMMIT() asm volatile("cp.async.commit_group;\n" ::: "memory")
template<int N> __device__ __forceinline__ void cp_wait() {
    asm volatile("cp.async.wait_group %0;\n" :: "n"(N) : "memory");
}

__device__ __forceinline__ void ldm_x4(uint32_t* r, uint32_t addr) {
    asm volatile("ldmatrix.sync.aligned.m8n8.x4.shared.b16 {%0,%1,%2,%3}, [%4];"
        : "=r"(r[0]), "=r"(r[1]), "=r"(r[2]), "=r"(r[3]) : "r"(addr));
}
__device__ __forceinline__ void ldm_x4_t(uint32_t* r, uint32_t addr) {
    asm volatile("ldmatrix.sync.aligned.m8n8.x4.trans.shared.b16 {%0,%1,%2,%3}, [%4];"
        : "=r"(r[0]), "=r"(r[1]), "=r"(r[2]), "=r"(r[3]) : "r"(addr));
}
__device__ __forceinline__ void mma_bf16(float* d, const uint32_t* a, uint32_t b0, uint32_t b1) {
    asm volatile("mma.sync.aligned.m16n8k16.row.col.f32.bf16.bf16.f32 "
        "{%0,%1,%2,%3}, {%4,%5,%6,%7}, {%8,%9}, {%0,%1,%2,%3};"
        : "+f"(d[0]), "+f"(d[1]), "+f"(d[2]), "+f"(d[3])
        : "r"(a[0]), "r"(a[1]), "r"(a[2]), "r"(a[3]), "r"(b0), "r"(b1));
}
__device__ __forceinline__ uint32_t pack_bf16(float a, float b) {
    __nv_bfloat162 t = __floats2bfloat162_rn(a, b);
    return *(uint32_t*)&t;
}

// ================ Split-precision conversion kernels ================
__device__ __forceinline__ void split4(float4 v, __nv_bfloat16* h, __nv_bfloat16* l) {
    h[0] = __float2bfloat16(v.x); l[0] = __float2bfloat16(v.x - __bfloat162float(h[0]));
    h[1] = __float2bfloat16(v.y); l[1] = __float2bfloat16(v.y - __bfloat162float(h[1]));
    h[2] = __float2bfloat16(v.z); l[2] = __float2bfloat16(v.z - __bfloat162float(h[2]));
    h[3] = __float2bfloat16(v.w); l[3] = __float2bfloat16(v.w - __bfloat162float(h[3]));
}
__device__ __forceinline__ void st8(__nv_bfloat16* p, const __nv_bfloat16* v) {
    *(uint2*)p = *(const uint2*)v;
}

// elementwise: src fp32 -> hi/lo bf16 buffers (same layout)
__global__ __launch_bounds__(256) void conv_split(const float* __restrict__ src,
                                                  __nv_bfloat16* __restrict__ dh,
                                                  __nv_bfloat16* __restrict__ dl,
                                                  long tot4)
{
    long idx = (long)blockIdx.x * 256 + threadIdx.x;
    if (idx >= tot4) return;
    float4 v = ((const float4*)src)[idx];
    __nv_bfloat16 h[4], l[4];
    split4(v, h, l);
    st8(dh + idx * 4, h);
    st8(dl + idx * 4, l);
}

// QKV weights: 3 sources stacked row-wise into combined [4096][2560] hi/lo
__global__ __launch_bounds__(256) void conv_split_qkv(const float* __restrict__ qw,
                                                      const float* __restrict__ kw,
                                                      const float* __restrict__ vw,
                                                      __nv_bfloat16* __restrict__ dh,
                                                      __nv_bfloat16* __restrict__ dl)
{
    const int kq = K1 >> 2;
    long idx = (long)blockIdx.x * 256 + threadIdx.x;
    long tot = (long)QKV_COLS * kq;
    if (idx >= tot) return;
    long r = idx / kq; int k4 = (int)(idx - r * kq);
    const float* src = (r < 2048) ? qw + r * (long)K1
                     : (r < 3072) ? kw + (r - 2048) * (long)K1
                                  : vw + (r - 3072) * (long)K1;
    float4 v = ((const float4*)src)[k4];
    __nv_bfloat16 h[4], l[4];
    split4(v, h, l);
    st8(dh + idx * 4, h);
    st8(dl + idx * 4, l);
}

// ================ bf16x3 HMMA GEMM, separate hi/lo operands ================
// C[m][n] = sum_k (Ah+Al)[m][k]*(Bh+Bl)[n][k], 3 terms (drop lo*lo).
// 128x128 CTA tile, 8 warps 2x4, warp tile 64x32, BK=64 per chunk.
// Stage = Ah|Al|Bh|Bl, 16KB each = 64KB; 3 stages = 192KB.
constexpr int G_STAGE = 65536;
constexpr int GEMM_SMEM = 3 * G_STAGE;   // 196608

__device__ __forceinline__ void load_chunk4(const char* Ah, const char* Al,
                                            const char* Bh, const char* Bl,
                                            size_t rowbytes, uint32_t smem_base,
                                            int stage, long kbyte, int tid)
{
    uint32_t s0 = smem_base + (uint32_t)stage * G_STAGE;
#pragma unroll
    for (int p = 0; p < 4; p++) {
        int idx = p * 256 + tid;
        int row = idx >> 3, j = idx & 7;
        uint32_t off = SWZ128((uint32_t)(row * 128 + j * 16));
        size_t go = (size_t)row * rowbytes + kbyte + j * 16;
        cp16(s0 + off,         Ah + go);
        cp16(s0 + 16384 + off, Al + go);
        cp16(s0 + 32768 + off, Bh + go);
        cp16(s0 + 49152 + off, Bl + go);
    }
    CP_COMMIT();
}

__global__ __launch_bounds__(256) void gemm_bf16x3(const __nv_bfloat16* __restrict__ Ahp,
                                                   const __nv_bfloat16* __restrict__ Alp,
                                                   const __nv_bfloat16* __restrict__ Bhp,
                                                   const __nv_bfloat16* __restrict__ Blp,
                                                   float* __restrict__ C,
                                                   int K, int Ntot)
{
    extern __shared__ char smem[];
    const uint32_t smem_base = smem_to_u32(smem);
    const int tid = threadIdx.x;
    const int wid = tid >> 5, lane = tid & 31;
    const int wm = wid & 1;
    const int wn = wid >> 1;
    const int n0 = blockIdx.x * 128;
    const int m0 = blockIdx.y * 128;

    const size_t rowbytes = (size_t)K * 2;
    const char* Ah = (const char*)Ahp + (size_t)m0 * rowbytes;
    const char* Al = (const char*)Alp + (size_t)m0 * rowbytes;
    const char* Bh = (const char*)Bhp + (size_t)n0 * rowbytes;
    const char* Bl = (const char*)Blp + (size_t)n0 * rowbytes;
    const int C_chunks = K / 64;

    load_chunk4(Ah, Al, Bh, Bl, rowbytes, smem_base, 0, 0, tid);
    load_chunk4(Ah, Al, Bh, Bl, rowbytes, smem_base, 1, 128, tid);
    load_chunk4(Ah, Al, Bh, Bl, rowbytes, smem_base, 2, 256, tid);

    float acc[4][4][4];
#pragma unroll
    for (int i = 0; i < 4; i++)
#pragma unroll
        for (int j = 0; j < 4; j++)
#pragma unroll
            for (int q = 0; q < 4; q++) acc[i][j][q] = 0.f;

    const int a_row_l = (lane & 15);
    const int a_hi    = (lane >> 4) * 16;
    const int b_row_l = (lane & 7) + ((lane >> 4) & 1) * 8;
    const int b_hi    = ((lane >> 3) & 1) * 16;

    for (int c = 0; c < C_chunks; c++) {
        const int s = c % 3;
        if (c + 2 < C_chunks)      cp_wait<2>();
        else if (c + 1 < C_chunks) cp_wait<1>();
        else                       cp_wait<0>();
        __syncthreads();

        const uint32_t sah = smem_base + (uint32_t)s * G_STAGE;
        const uint32_t sal = sah + 16384;
        const uint32_t sbh = sah + 32768;
        const uint32_t sbl = sah + 49152;

#pragma unroll
        for (int ks = 0; ks < 4; ks++) {
            // B fragments (hi + lo), 32 cols each
            uint32_t bh[2][4], bl[2][4];
#pragma unroll
            for (int nb = 0; nb < 2; nb++) {
                int row = wn * 32 + nb * 16 + b_row_l;
                uint32_t kb = (uint32_t)(ks * 32 + b_hi) ^ ((uint32_t)(row & 7) << 4);
                ldm_x4(bh[nb], sbh + row * 128 + kb);
                ldm_x4(bl[nb], sbl + row * 128 + kb);
            }
            // A hi fragments; hi*hi and hi*lo
            uint32_t a[4][4];
#pragma unroll
            for (int mf = 0; mf < 4; mf++) {
                int row = wm * 64 + mf * 16 + a_row_l;
                uint32_t kb = (uint32_t)(ks * 32 + a_hi) ^ ((uint32_t)(row & 7) << 4);
                ldm_x4(a[mf], sah + row * 128 + kb);
            }
#pragma unroll
            for (int mf = 0; mf < 4; mf++) {
#pragma unroll
                for (int nf = 0; nf < 4; nf++) {
                    mma_bf16(acc[mf][nf], a[mf], bh[nf >> 1][(nf & 1) * 2], bh[nf >> 1][(nf & 1) * 2 + 1]);
                    mma_bf16(acc[mf][nf], a[mf], bl[nf >> 1][(nf & 1) * 2], bl[nf >> 1][(nf & 1) * 2 + 1]);
                }
            }
            // A lo fragments (reuse regs); lo*hi
#pragma unroll
            for (int mf = 0; mf < 4; mf++) {
                int row = wm * 64 + mf * 16 + a_row_l;
                uint32_t kb = (uint32_t)(ks * 32 + a_hi) ^ ((uint32_t)(row & 7) << 4);
                ldm_x4(a[mf], sal + row * 128 + kb);
            }
#pragma unroll
            for (int mf = 0; mf < 4; mf++) {
#pragma unroll
                for (int nf = 0; nf < 4; nf++)
                    mma_bf16(acc[mf][nf], a[mf], bh[nf >> 1][(nf & 1) * 2], bh[nf >> 1][(nf & 1) * 2 + 1]);
            }
        }
        __syncthreads();
        if (c + 3 < C_chunks)
            load_chunk4(Ah, Al, Bh, Bl, rowbytes, smem_base, s, (long)(c + 3) * 128, tid);
    }

    const int er = lane >> 2;
    const int ec = (lane & 3) * 2;
#pragma unroll
    for (int mf = 0; mf < 4; mf++) {
        const int rbase = m0 + wm * 64 + mf * 16 + er;
#pragma unroll
        for (int nf = 0; nf < 4; nf++) {
            const int cbase = n0 + wn * 32 + nf * 8 + ec;
            float* p0 = C + (size_t)rbase * Ntot + cbase;
            float* p1 = C + (size_t)(rbase + 8) * Ntot + cbase;
            *(float2*)p0 = make_float2(acc[mf][nf][0], acc[mf][nf][1]);
            *(float2*)p1 = make_float2(acc[mf][nf][2], acc[mf][nf][3]);
        }
    }
}

// ---------------- RMSNorm + RoPE -> bf16 hi/lo split (unchanged) ----------------
__global__ __launch_bounds__(256) void norm_rope_kernel(
    const float* __restrict__ cosp, const float* __restrict__ sinp,
    const float* __restrict__ qn_w, const float* __restrict__ kn_w)
{
    const int token = blockIdx.x;
    const int slot  = blockIdx.y;
    const int d     = threadIdx.x;
    const int b = token / S;
    const int s = token % S;

    const float* row = g_qkv + (size_t)token * QKV_COLS;
    float x;
    if (slot < 8)       x = row[slot * HD + d];
    else if (slot < 12) x = row[2048 + (slot - 8) * HD + d];
    else                x = row[3072 + (slot - 12) * HD + d];

    if (slot >= 12) {
        size_t o = (((size_t)b * HKV + (slot - 12)) * S + s) * HD + d;
        __nv_bfloat16 hb = __float2bfloat16(x);
        g_vh[o] = hb;
        g_vl[o] = __float2bfloat16(x - __bfloat162float(hb));
        return;
    }

    __shared__ float red[8];
    __shared__ float xs[HD];
    float ss = x * x;
#pragma unroll
    for (int o = 16; o > 0; o >>= 1) ss += __shfl_xor_sync(0xffffffffu, ss, o);
    if ((d & 31) == 0) red[d >> 5] = ss;
    __syncthreads();
    float tot = red[0];
#pragma unroll
    for (int i = 1; i < 8; i++) tot += red[i];
    const float scale = rsqrtf(tot * (1.0f / HD) + EPS);

    const float* nw = (slot < 8) ? qn_w : kn_w;
    const float xn = x * scale * (1.0f + nw[d]);
    xs[d] = xn;
    __syncthreads();

    const float rot = (d < HD/2) ? -xs[d + HD/2] : xs[d - HD/2];
    const size_t csi = ((size_t)b * S + s) * HD + d;
    const float out = xn * cosp[csi] + rot * sinp[csi];

    __nv_bfloat16 hb = __float2bfloat16(out);
    __nv_bfloat16 lb = __float2bfloat16(out - __bfloat162float(hb));
    if (slot < 8) {
        size_t o = (((size_t)b * H + slot) * S + s) * HD + d;
        g_qh[o] = hb; g_ql[o] = lb;
    } else {
        size_t o = (((size_t)b * HKV + (slot - 8)) * S + s) * HD + d;
        g_kh[o] = hb; g_kl[o] = lb;
    }
}

// ---------------- Flash attention v2 (R9 shape) + poly softcap ----------------
// BM=64 q rows, BN=32 keys/tile, 128 threads (4 warps, each m16 x full N).
constexpr int FLASH2_SMEM = 196608;   // 64KB Q + 2*64KB stages

__global__ __launch_bounds__(128) void flash_mma()
{
    extern __shared__ char fsm[];
    const uint32_t sb0 = smem_to_u32(fsm);
    const uint32_t sQh = sb0, sQl = sb0 + 32768;

    const int qt = blockIdx.x;
    const int h  = blockIdx.y;
    const int b  = blockIdx.z;
    const int q0 = qt * 64;
    const int hk = h >> 1;

    const int tid = threadIdx.x, warp = tid >> 5, lane = tid & 31;

    const __nv_bfloat16* Qhp = g_qh + (((size_t)b * H   + h ) * S + q0) * HD;
    const __nv_bfloat16* Qlp = g_ql + (((size_t)b * H   + h ) * S + q0) * HD;
    const __nv_bfloat16* Khp = g_kh + (((size_t)b * HKV + hk) * S) * HD;
    const __nv_bfloat16* Klp = g_kl + (((size_t)b * HKV + hk) * S) * HD;
    const __nv_bfloat16* Vhp = g_vh + (((size_t)b * HKV + hk) * S) * HD;
    const __nv_bfloat16* Vlp = g_vl + (((size_t)b * HKV + hk) * S) * HD;

    for (int u = tid; u < 2048; u += 128) {
        int row = u >> 5, c = u & 31;
        uint32_t off = (uint32_t)row * 512 + (((uint32_t)c * 16) ^ (((uint32_t)row & 7) << 4));
        cp16(sQh + off, Qhp + (size_t)row * HD + c * 8);
        cp16(sQl + off, Qlp + (size_t)row * HD + c * 8);
    }
    CP_COMMIT();

    const int ntiles = 2 * (qt + 1);

#pragma unroll 1
    for (int pt = 0; pt < 2; pt++) {
        uint32_t sB = sb0 + 65536 + pt * 65536;
        int j0 = pt * 32;
        for (int u = tid; u < 1024; u += 128) {
            int row = u >> 5, c = u & 31;
            uint32_t off = (uint32_t)row * 512 + (((uint32_t)c * 16) ^ (((uint32_t)row & 7) << 4));
            size_t g = (size_t)(j0 + row) * HD + c * 8;
            cp16(sB + off,         Khp + g);
            cp16(sB + 16384 + off, Klp + g);
            cp16(sB + 32768 + off, Vhp + g);
            cp16(sB + 49152 + off, Vlp + g);
        }
        CP_COMMIT();
    }

    float acc[32][4];
#pragma unroll
    for (int i = 0; i < 32; i++) { acc[i][0]=0.f; acc[i][1]=0.f; acc[i][2]=0.f; acc[i][3]=0.f; }
    float mrow0 = -1e30f, mrow1 = -1e30f, lrow0 = 0.f, lrow1 = 0.f;

    const int rA = q0 + warp * 16 + (lane >> 2);

    const int arow = warp * 16 + (lane & 15);
    const uint32_t aswz = ((uint32_t)(arow & 7)) << 4;
    const uint32_t asel = (uint32_t)(lane >> 4) * 16;
    const int brow = (lane & 7) + ((lane >> 4) & 1) * 8;
    const uint32_t bswz = ((uint32_t)(brow & 7)) << 4;
    const uint32_t bsel = (uint32_t)((lane >> 3) & 1) * 16;
    const int vlanerow = (lane & 7) + ((lane >> 3) & 1) * 8;
    const uint32_t vdsel = (uint32_t)((lane >> 4) & 1) * 16;

    for (int t = 0; t < ntiles; t++) {
        if (t + 1 < ntiles) cp_wait<1>(); else cp_wait<0>();
        __syncthreads();
        const uint32_t sK = sb0 + 65536 + (t & 1) * 65536;
        const uint32_t sV = sK + 32768;

        // ---- QK^T: m16 x n32, K=256, 3 split terms ----
        float sc[4][4];
#pragma unroll
        for (int i = 0; i < 4; i++) { sc[i][0]=0.f; sc[i][1]=0.f; sc[i][2]=0.f; sc[i][3]=0.f; }

#pragma unroll 4
        for (int kc = 0; kc < 16; kc++) {
            uint32_t kb_a = ((uint32_t)(kc * 32) + asel) ^ aswz;
            uint32_t aq[4], al[4];
            ldm_x4(aq, sQh + (uint32_t)arow * 512 + kb_a);
            ldm_x4(al, sQl + (uint32_t)arow * 512 + kb_a);
            uint32_t kb_b = ((uint32_t)(kc * 32) + bsel) ^ bswz;
            uint32_t bh0[4], bh1[4], bl0[4], bl1[4];
            ldm_x4(bh0, sK + (uint32_t)brow * 512 + kb_b);
            ldm_x4(bh1, sK + (uint32_t)(brow + 16) * 512 + kb_b);
            ldm_x4(bl0, sK + 16384 + (uint32_t)brow * 512 + kb_b);
            ldm_x4(bl1, sK + 16384 + (uint32_t)(brow + 16) * 512 + kb_b);

            mma_bf16(sc[0], aq, bh0[0], bh0[1]); mma_bf16(sc[0], al, bh0[0], bh0[1]); mma_bf16(sc[0], aq, bl0[0], bl0[1]);
            mma_bf16(sc[1], aq, bh0[2], bh0[3]); mma_bf16(sc[1], al, bh0[2], bh0[3]); mma_bf16(sc[1], aq, bl0[2], bl0[3]);
            mma_bf16(sc[2], aq, bh1[0], bh1[1]); mma_bf16(sc[2], al, bh1[0], bh1[1]); mma_bf16(sc[2], aq, bl1[0], bl1[1]);
            mma_bf16(sc[3], aq, bh1[2], bh1[3]); mma_bf16(sc[3], al, bh1[2], bh1[3]); mma_bf16(sc[3], aq, bl1[2], bl1[3]);
        }

        // ---- poly softcap + causal mask + online softmax ----
        const int j0 = t * 32;
        float mn0 = mrow0, mn1 = mrow1;
#pragma unroll
        for (int nf = 0; nf < 4; nf++) {
            const int cb = j0 + nf * 8 + (lane & 3) * 2;
#pragma unroll
            for (int e = 0; e < 4; e++) {
                float w = sc[nf][e] * SCALING;
                const float tt = w * (1.0f / SOFTCAP);
                w = w * (1.0f - 0.33333333f * tt * tt);   // C*tanh(w/C), |tt|<=0.004
                const int col = cb + (e & 1);
                const int rowg = (e < 2) ? rA : (rA + 8);
                if (col > rowg) w = NEGBIG;
                sc[nf][e] = w;
                if (e < 2) mn0 = fmaxf(mn0, w); else mn1 = fmaxf(mn1, w);
            }
        }
        mn0 = fmaxf(mn0, __shfl_xor_sync(0xffffffffu, mn0, 1));
        mn0 = fmaxf(mn0, __shfl_xor_sync(0xffffffffu, mn0, 2));
        mn1 = fmaxf(mn1, __shfl_xor_sync(0xffffffffu, mn1, 1));
        mn1 = fmaxf(mn1, __shfl_xor_sync(0xffffffffu, mn1, 2));
        const float corr0 = __expf(mrow0 - mn0);
        const float corr1 = __expf(mrow1 - mn1);
        mrow0 = mn0; mrow1 = mn1;

        float ps0 = 0.f, ps1 = 0.f;
        uint32_t aphi[2][4], aplo[2][4];
#pragma unroll
        for (int f = 0; f < 2; f++) {
#pragma unroll
            for (int hf = 0; hf < 2; hf++) {
                const int nf = 2 * f + hf;
                float p00 = __expf(sc[nf][0] - mn0), p01 = __expf(sc[nf][1] - mn0);
                float p10 = __expf(sc[nf][2] - mn1), p11 = __expf(sc[nf][3] - mn1);
                ps0 += p00 + p01; ps1 += p10 + p11;
                float h00 = __bfloat162float(__float2bfloat16(p00));
                float h01 = __bfloat162float(__float2bfloat16(p01));
                float h10 = __bfloat162float(__float2bfloat16(p10));
                float h11 = __bfloat162float(__float2bfloat16(p11));
                aphi[f][hf * 2 + 0] = pack_bf16(h00, h01);
                aphi[f][hf * 2 + 1] = pack_bf16(h10, h11);
                aplo[f][hf * 2 + 0] = pack_bf16(p00 - h00, p01 - h01);
                aplo[f][hf * 2 + 1] = pack_bf16(p10 - h10, p11 - h11);
            }
        }
        ps0 += __shfl_xor_sync(0xffffffffu, ps0, 1);
        ps0 += __shfl_xor_sync(0xffffffffu, ps0, 2);
        ps1 += __shfl_xor_sync(0xffffffffu, ps1, 1);
        ps1 += __shfl_xor_sync(0xffffffffu, ps1, 2);
        lrow0 = lrow0 * corr0 + ps0;
        lrow1 = lrow1 * corr1 + ps1;

#pragma unroll
        for (int nf = 0; nf < 32; nf++) {
            acc[nf][0] *= corr0; acc[nf][1] *= corr0;
            acc[nf][2] *= corr1; acc[nf][3] *= corr1;
        }

        // ---- PV: A = p frags (regs), B = V via trans ldmatrix; 3 split terms ----
#pragma unroll
        for (int kf = 0; kf < 2; kf++) {
            const int jrow = kf * 16 + vlanerow;
            const uint32_t vbase = sV + (uint32_t)jrow * 512;
            const uint32_t vswz = ((uint32_t)(jrow & 7)) << 4;
#pragma unroll
            for (int g16 = 0; g16 < 16; g16++) {
                uint32_t dby = ((uint32_t)(g16 * 32) + vdsel) ^ vswz;
                uint32_t vhf[4], vlf[4];
                ldm_x4_t(vhf, vbase + dby);
                ldm_x4_t(vlf, vbase + 16384 + dby);
                mma_bf16(acc[2 * g16],     aphi[kf], vhf[0], vhf[1]);
                mma_bf16(acc[2 * g16],     aplo[kf], vhf[0], vhf[1]);
                mma_bf16(acc[2 * g16],     aphi[kf], vlf[0], vlf[1]);
                mma_bf16(acc[2 * g16 + 1], aphi[kf], vhf[2], vhf[3]);
                mma_bf16(acc[2 * g16 + 1], aplo[kf], vhf[2], vhf[3]);
                mma_bf16(acc[2 * g16 + 1], aphi[kf], vlf[2], vlf[3]);
            }
        }

        __syncthreads();
        if (t + 2 < ntiles) {
            uint32_t sB = sb0 + 65536 + (t & 1) * 65536;
            int j0n = (t + 2) * 32;
            for (int u = tid; u < 1024; u += 128) {
                int row = u >> 5, c = u & 31;
                uint32_t off = (uint32_t)row * 512 + (((uint32_t)c * 16) ^ (((uint32_t)row & 7) << 4));
                size_t g = (size_t)(j0n + row) * HD + c * 8;
                cp16(sB + off,         Khp + g);
                cp16(sB + 16384 + off, Klp + g);
                cp16(sB + 32768 + off, Vhp + g);
                cp16(sB + 49152 + off, Vlp + g);
            }
            CP_COMMIT();
        }
    }

    // ---- epilogue: normalize + hi/lo split-write into g_ah/g_al ----
    const float inv0 = 1.0f / lrow0;
    const float inv1 = 1.0f / lrow1;
    const size_t tokA = (size_t)b * S + q0 + warp * 16 + (lane >> 2);
    __nv_bfloat16* rowAh = g_ah + tokA * (size_t)K2 + h * HD;
    __nv_bfloat16* rowAl = g_al + tokA * (size_t)K2 + h * HD;
    __nv_bfloat16* rowBh = g_ah + (tokA + 8) * (size_t)K2 + h * HD;
    __nv_bfloat16* rowBl = g_al + (tokA + 8) * (size_t)K2 + h * HD;
#pragma unroll
    for (int nf = 0; nf < 32; nf++) {
        const int d = nf * 8 + (lane & 3) * 2;
        {
            float v0 = acc[nf][0] * inv0, v1 = acc[nf][1] * inv0;
            float h0 = __bfloat162float(__float2bfloat16(v0));
            float h1 = __bfloat162float(__float2bfloat16(v1));
            *(__nv_bfloat162*)(rowAh + d) = __floats2bfloat162_rn(h0, h1);
            *(__nv_bfloat162*)(rowAl + d) = __floats2bfloat162_rn(v0 - h0, v1 - h1);
        }
        {
            float v0 = acc[nf][2] * inv1, v1 = acc[nf][3] * inv1;
            float h0 = __bfloat162float(__float2bfloat16(v0));
            float h1 = __bfloat162float(__float2bfloat16(v1));
            *(__nv_bfloat162*)(rowBh + d) = __floats2bfloat162_rn(h0, h1);
            *(__nv_bfloat162*)(rowBl + d) = __floats2bfloat162_rn(v0 - h0, v1 - h1);
        }
    }
}

// ---------------- Host launch ----------------
extern "C" void kernel_launch(void* const* d_in, const int* in_sizes, int n_in,
                              void* d_out, int out_size)
{
    const float* x    = (const float*)d_in[0];
    const float* cosp = (const float*)d_in[1];
    const float* sinp = (const float*)d_in[2];
    const float* q_w  = (const float*)d_in[4];
    const float* k_w  = (const float*)d_in[5];
    const float* v_w  = (const float*)d_in[6];
    const float* o_w  = (const float*)d_in[7];
    const float* qn_w = (const float*)d_in[8];
    const float* kn_w = (const float*)d_in[9];
    float* out = (float*)d_out;

    void *p_qkv, *p_xh, *p_xl, *p_wh, *p_wl, *p_ah, *p_al, *p_owh, *p_owl;
    cudaGetSymbolAddress(&p_qkv, g_qkv);
    cudaGetSymbolAddress(&p_xh,  g_xh);
    cudaGetSymbolAddress(&p_xl,  g_xl);
    cudaGetSymbolAddress(&p_wh,  g_wh);
    cudaGetSymbolAddress(&p_wl,  g_wl);
    cudaGetSymbolAddress(&p_ah,  g_ah);
    cudaGetSymbolAddress(&p_al,  g_al);
    cudaGetSymbolAddress(&p_owh, g_owh);
    cudaGetSymbolAddress(&p_owl, g_owl);
    float* qkv = (float*)p_qkv;
    __nv_bfloat16* xh  = (__nv_bfloat16*)p_xh;
    __nv_bfloat16* xl  = (__nv_bfloat16*)p_xl;
    __nv_bfloat16* wh  = (__nv_bfloat16*)p_wh;
    __nv_bfloat16* wl  = (__nv_bfloat16*)p_wl;
    __nv_bfloat16* ah  = (__nv_bfloat16*)p_ah;
    __nv_bfloat16* al  = (__nv_bfloat16*)p_al;
    __nv_bfloat16* owh = (__nv_bfloat16*)p_owh;
    __nv_bfloat16* owl = (__nv_bfloat16*)p_owl;

    cudaFuncSetAttribute(gemm_bf16x3, cudaFuncAttributeMaxDynamicSharedMemorySize, GEMM_SMEM);
    cudaFuncSetAttribute(flash_mma,   cudaFuncAttributeMaxDynamicSharedMemorySize, FLASH2_SMEM);

    // 1) split-convert x and QKV weights (separate hi/lo buffers)
    {
        long tot = (long)NTOK * (K1 / 4);
        conv_split<<<(unsigned)((tot + 255) / 256), 256>>>(x, xh, xl, tot);
        long totw = (long)QKV_COLS * (K1 / 4);
        conv_split_qkv<<<(unsigned)((totw + 255) / 256), 256>>>(q_w, k_w, v_w, wh, wl);
    }
    // 2) QKV projection (3-term HMMA, separate hi/lo)
    gemm_bf16x3<<<dim3(QKV_COLS / 128, NTOK / 128), 256, GEMM_SMEM>>>(xh, xl, wh, wl, qkv, K1, QKV_COLS);

    // 3) RMSNorm + RoPE + bf16 hi/lo split
    norm_rope_kernel<<<dim3(NTOK, 16), 256>>>(cosp, sinp, qn_w, kn_w);

    // 4) Flash attention v2 (writes g_ah/g_al)
    flash_mma<<<dim3(S / 64, H, B), 128, FLASH2_SMEM>>>();

    // 5) split-convert O weights
    {
        long totw = (long)D * (K2 / 4);
        conv_split<<<(unsigned)((totw + 255) / 256), 256>>>(o_w, owh, owl, totw);
    }
    // 6) O projection
    gemm_bf16x3<<<dim3(D / 128, NTOK / 128), 256, GEMM_SMEM>>>(ah, al, owh, owl, out, K2, D);
}

// round 13
// speedup vs baseline: 1.0945x; 1.0138x over previous
#include <cuda_runtime.h>
#include <cuda_bf16.h>
#include <math.h>
#include <cstdint>

// ---------------- Problem constants ----------------
constexpr int B   = 2;
constexpr int S   = 2048;
constexpr int D   = 2560;
constexpr int H   = 8;
constexpr int HKV = 4;
constexpr int HD  = 256;
constexpr int NTOK = B * S;                 // 4096
constexpr int QKV_COLS = H*HD + 2*HKV*HD;   // 4096
constexpr float EPS = 1e-6f;
constexpr float SCALING = 0.0625f;
constexpr float SOFTCAP = 4096.0f;
constexpr float NEGBIG = -1e9f;

constexpr int K1 = D;          // 2560
constexpr int K2 = H * HD;     // 2048

// ---------------- Scratch (device globals) ----------------
__device__ float g_qkv[(size_t)NTOK * QKV_COLS];
__device__ __nv_bfloat16 g_xh [(size_t)NTOK * K1];
__device__ __nv_bfloat16 g_xl [(size_t)NTOK * K1];
__device__ __nv_bfloat16 g_wh [(size_t)QKV_COLS * K1];
__device__ __nv_bfloat16 g_wl [(size_t)QKV_COLS * K1];
__device__ __nv_bfloat16 g_ah [(size_t)NTOK * K2];
__device__ __nv_bfloat16 g_al [(size_t)NTOK * K2];
__device__ __nv_bfloat16 g_owh[(size_t)D * K2];
__device__ __nv_bfloat16 g_owl[(size_t)D * K2];
__device__ __nv_bfloat16 g_qh[(size_t)B * H   * S * HD];
__device__ __nv_bfloat16 g_ql[(size_t)B * H   * S * HD];
__device__ __nv_bfloat16 g_kh[(size_t)B * HKV * S * HD];
__device__ __nv_bfloat16 g_kl[(size_t)B * HKV * S * HD];
__device__ __nv_bfloat16 g_vh[(size_t)B * HKV * S * HD];
__device__ __nv_bfloat16 g_vl[(size_t)B * HKV * S * HD];

// ================= helpers =================
__device__ __forceinline__ uint32_t smem_to_u32(const void* p) {
    uint32_t a;
    asm("{ .reg .u64 t; cvta.to.shared.u64 t, %1; cvt.u32.u64 %0, t; }" : "=r"(a) : "l"(p));
    return a;
}

__device__ __forceinline__ void cp16(uint32_t s, const void* g) {
    asm volatile("cp.async.cg.shared.global [%0], [%1], 16;\n" :: "r"(s), "l"(g));
}
#define CP_COMMIT() asm volatile("cp.async.commit_group;\n" ::: "memory")
template<int N> __device__ __forceinline__ void cp_wait() {
    asm volatile("cp.async.wait_group %0;\n" :: "n"(N) : "memory");
}

__device__ __forceinline__ void ldm_x4(uint32_t* r, uint32_t addr) {
    asm volatile("ldmatrix.sync.aligned.m8n8.x4.shared.b16 {%0,%1,%2,%3}, [%4];"
        : "=r"(r[0]), "=r"(r[1]), "=r"(r[2]), "=r"(r[3]) : "r"(addr));
}
__device__ __forceinline__ void ldm_x4_t(uint32_t* r, uint32_t addr) {
    asm volatile("ldmatrix.sync.aligned.m8n8.x4.trans.shared.b16 {%0,%1,%2,%3}, [%4];"
        : "=r"(r[0]), "=r"(r[1]), "=r"(r[2]), "=r"(r[3]) : "r"(addr));
}
__device__ __forceinline__ void mma_bf16(float* d, const uint32_t* a, uint32_t b0, uint32_t b1) {
    asm volatile("mma.sync.aligned.m16n8k16.row.col.f32.bf16.bf16.f32 "
        "{%0,%1,%2,%3}, {%4,%5,%6,%7}, {%8,%9}, {%0,%1,%2,%3};"
        : "+f"(d[0]), "+f"(d[1]), "+f"(d[2]), "+f"(d[3])
        : "r"(a[0]), "r"(a[1]), "r"(a[2]), "r"(a[3]), "r"(b0), "r"(b1));
}
__device__ __forceinline__ uint32_t pack_bf16(float a, float b) {
    __nv_bfloat162 t = __floats2bfloat162_rn(a, b);
    return *(uint32_t*)&t;
}

// ================ Split-precision conversion kernels ================
__device__ __forceinline__ void split4(float4 v, __nv_bfloat16* h, __nv_bfloat16* l) {
    h[0] = __float2bfloat16(v.x); l[0] = __float2bfloat16(v.x - __bfloat162float(h[0]));
    h[1] = __float2bfloat16(v.y); l[1] = __float2bfloat16(v.y - __bfloat162float(h[1]));
    h[2] = __float2bfloat16(v.z); l[2] = __float2bfloat16(v.z - __bfloat162float(h[2]));
    h[3] = __float2bfloat16(v.w); l[3] = __float2bfloat16(v.w - __bfloat162float(h[3]));
}
__device__ __forceinline__ void st8(__nv_bfloat16* p, const __nv_bfloat16* v) {
    *(uint2*)p = *(const uint2*)v;
}

__global__ __launch_bounds__(256) void conv_split(const float* __restrict__ src,
                                                  __nv_bfloat16* __restrict__ dh,
                                                  __nv_bfloat16* __restrict__ dl,
                                                  long tot4)
{
    long idx = (long)blockIdx.x * 256 + threadIdx.x;
    if (idx >= tot4) return;
    float4 v = ((const float4*)src)[idx];
    __nv_bfloat16 h[4], l[4];
    split4(v, h, l);
    st8(dh + idx * 4, h);
    st8(dl + idx * 4, l);
}

__global__ __launch_bounds__(256) void conv_split_qkv(const float* __restrict__ qw,
                                                      const float* __restrict__ kw,
                                                      const float* __restrict__ vw,
                                                      __nv_bfloat16* __restrict__ dh,
                                                      __nv_bfloat16* __restrict__ dl)
{
    const int kq = K1 >> 2;
    long idx = (long)blockIdx.x * 256 + threadIdx.x;
    long tot = (long)QKV_COLS * kq;
    if (idx >= tot) return;
    long r = idx / kq; int k4 = (int)(idx - r * kq);
    const float* src = (r < 2048) ? qw + r * (long)K1
                     : (r < 3072) ? kw + (r - 2048) * (long)K1
                                  : vw + (r - 3072) * (long)K1;
    float4 v = ((const float4*)src)[k4];
    __nv_bfloat16 h[4], l[4];
    split4(v, h, l);
    st8(dh + idx * 4, h);
    st8(dl + idx * 4, l);
}

// ================ bf16x3 HMMA GEMM, BK=32, 2 CTAs/SM ================
// C[m][n] = (Ah+Al)[m][k]*(Bh+Bl)[n][k], 3 terms (drop lo*lo).
// 128x128 CTA tile, 8 warps 2x4, warp tile 64x32, BK=32 per chunk.
// 64-byte rows, SW64 swizzle: off ^= ((off>>3)&0x30); stage 32KB, 3 stages = 96KB.
constexpr int G_STAGE = 32768;
constexpr int GEMM_SMEM = 3 * G_STAGE;   // 98304

__device__ __forceinline__ uint32_t phz(int row) { return ((uint32_t)(row >> 1) & 3u) << 4; }

__device__ __forceinline__ void load_chunk4(const char* Ah, const char* Al,
                                            const char* Bh, const char* Bl,
                                            size_t rowbytes, uint32_t smem_base,
                                            int stage, long kbyte, int tid)
{
    uint32_t s0 = smem_base + (uint32_t)stage * G_STAGE;
#pragma unroll
    for (int p = 0; p < 2; p++) {
        int idx = p * 256 + tid;
        int row = idx >> 2, j = idx & 3;
        uint32_t off = (uint32_t)row * 64 + (((uint32_t)j * 16) ^ phz(row));
        size_t go = (size_t)row * rowbytes + kbyte + j * 16;
        cp16(s0 + off,         Ah + go);
        cp16(s0 + 8192 + off,  Al + go);
        cp16(s0 + 16384 + off, Bh + go);
        cp16(s0 + 24576 + off, Bl + go);
    }
    CP_COMMIT();
}

__global__ __launch_bounds__(256, 2) void gemm_bf16x3(const __nv_bfloat16* __restrict__ Ahp,
                                                      const __nv_bfloat16* __restrict__ Alp,
                                                      const __nv_bfloat16* __restrict__ Bhp,
                                                      const __nv_bfloat16* __restrict__ Blp,
                                                      float* __restrict__ C,
                                                      int K, int Ntot)
{
    extern __shared__ char smem[];
    const uint32_t smem_base = smem_to_u32(smem);
    const int tid = threadIdx.x;
    const int wid = tid >> 5, lane = tid & 31;
    const int wm = wid & 1;
    const int wn = wid >> 1;
    const int n0 = blockIdx.x * 128;
    const int m0 = blockIdx.y * 128;

    const size_t rowbytes = (size_t)K * 2;
    const char* Ah = (const char*)Ahp + (size_t)m0 * rowbytes;
    const char* Al = (const char*)Alp + (size_t)m0 * rowbytes;
    const char* Bh = (const char*)Bhp + (size_t)n0 * rowbytes;
    const char* Bl = (const char*)Blp + (size_t)n0 * rowbytes;
    const int C_chunks = K / 32;

    load_chunk4(Ah, Al, Bh, Bl, rowbytes, smem_base, 0, 0, tid);
    load_chunk4(Ah, Al, Bh, Bl, rowbytes, smem_base, 1, 64, tid);
    load_chunk4(Ah, Al, Bh, Bl, rowbytes, smem_base, 2, 128, tid);

    float acc[4][4][4];
#pragma unroll
    for (int i = 0; i < 4; i++)
#pragma unroll
        for (int j = 0; j < 4; j++)
#pragma unroll
            for (int q = 0; q < 4; q++) acc[i][j][q] = 0.f;

    const int a_row_l = (lane & 15);
    const uint32_t a_hi = (uint32_t)(lane >> 4) * 16;
    const int b_row_l = (lane & 7) + ((lane >> 4) & 1) * 8;
    const uint32_t b_hi = (uint32_t)((lane >> 3) & 1) * 16;

    for (int c = 0; c < C_chunks; c++) {
        const int s = c % 3;
        if (c + 2 < C_chunks)      cp_wait<2>();
        else if (c + 1 < C_chunks) cp_wait<1>();
        else                       cp_wait<0>();
        __syncthreads();

        const uint32_t sah = smem_base + (uint32_t)s * G_STAGE;
        const uint32_t sal = sah + 8192;
        const uint32_t sbh = sah + 16384;
        const uint32_t sbl = sah + 24576;

#pragma unroll
        for (int ks = 0; ks < 2; ks++) {
            uint32_t bh[2][4], bl[2][4];
#pragma unroll
            for (int nb = 0; nb < 2; nb++) {
                int row = wn * 32 + nb * 16 + b_row_l;
                uint32_t kb = ((uint32_t)(ks * 32) + b_hi) ^ phz(row);
                ldm_x4(bh[nb], sbh + (uint32_t)row * 64 + kb);
                ldm_x4(bl[nb], sbl + (uint32_t)row * 64 + kb);
            }
            uint32_t a[4][4];
#pragma unroll
            for (int mf = 0; mf < 4; mf++) {
                int row = wm * 64 + mf * 16 + a_row_l;
                uint32_t kb = ((uint32_t)(ks * 32) + a_hi) ^ phz(row);
                ldm_x4(a[mf], sah + (uint32_t)row * 64 + kb);
            }
#pragma unroll
            for (int mf = 0; mf < 4; mf++) {
#pragma unroll
                for (int nf = 0; nf < 4; nf++) {
                    mma_bf16(acc[mf][nf], a[mf], bh[nf >> 1][(nf & 1) * 2], bh[nf >> 1][(nf & 1) * 2 + 1]);
                    mma_bf16(acc[mf][nf], a[mf], bl[nf >> 1][(nf & 1) * 2], bl[nf >> 1][(nf & 1) * 2 + 1]);
                }
            }
#pragma unroll
            for (int mf = 0; mf < 4; mf++) {
                int row = wm * 64 + mf * 16 + a_row_l;
                uint32_t kb = ((uint32_t)(ks * 32) + a_hi) ^ phz(row);
                ldm_x4(a[mf], sal + (uint32_t)row * 64 + kb);
            }
#pragma unroll
            for (int mf = 0; mf < 4; mf++) {
#pragma unroll
                for (int nf = 0; nf < 4; nf++)
                    mma_bf16(acc[mf][nf], a[mf], bh[nf >> 1][(nf & 1) * 2], bh[nf >> 1][(nf & 1) * 2 + 1]);
            }
        }
        __syncthreads();
        if (c + 3 < C_chunks)
            load_chunk4(Ah, Al, Bh, Bl, rowbytes, smem_base, s, (long)(c + 3) * 64, tid);
    }

    const int er = lane >> 2;
    const int ec = (lane & 3) * 2;
#pragma unroll
    for (int mf = 0; mf < 4; mf++) {
        const int rbase = m0 + wm * 64 + mf * 16 + er;
#pragma unroll
        for (int nf = 0; nf < 4; nf++) {
            const int cbase = n0 + wn * 32 + nf * 8 + ec;
            float* p0 = C + (size_t)rbase * Ntot + cbase;
            float* p1 = C + (size_t)(rbase + 8) * Ntot + cbase;
            *(float2*)p0 = make_float2(acc[mf][nf][0], acc[mf][nf][1]);
            *(float2*)p1 = make_float2(acc[mf][nf][2], acc[mf][nf][3]);
        }
    }
}

// ---------------- RMSNorm + RoPE: warp-per-head-row, no block syncs ----------------
// grid (NTOK, 2), 256 thr = 8 warps; warp w handles slot = by*8+w.
// Lane l owns d = l*4 (chunk0) and d = 128+l*4 (chunk1) -> rotate pairs stay in-lane.
__global__ __launch_bounds__(256) void norm_rope_kernel(
    const float* __restrict__ cosp, const float* __restrict__ sinp,
    const float* __restrict__ qn_w, const float* __restrict__ kn_w)
{
    const int token = blockIdx.x;
    const int w = threadIdx.x >> 5, lane = threadIdx.x & 31;
    const int slot = blockIdx.y * 8 + w;
    const int b = token / S;
    const int s = token % S;

    const float* row = g_qkv + (size_t)token * QKV_COLS;
    const float* src = (slot < 8)  ? row + slot * HD
                     : (slot < 12) ? row + 2048 + (slot - 8) * HD
                                   : row + 3072 + (slot - 12) * HD;
    const int d0 = lane * 4;
    float4 x0 = *(const float4*)(src + d0);
    float4 x1 = *(const float4*)(src + 128 + d0);

    if (slot >= 12) {
        size_t o = (((size_t)b * HKV + (slot - 12)) * S + s) * HD;
        __nv_bfloat16 h[4], l[4];
        split4(x0, h, l); st8(g_vh + o + d0, h); st8(g_vl + o + d0, l);
        split4(x1, h, l); st8(g_vh + o + 128 + d0, h); st8(g_vl + o + 128 + d0, l);
        return;
    }

    float ss = x0.x*x0.x + x0.y*x0.y + x0.z*x0.z + x0.w*x0.w
             + x1.x*x1.x + x1.y*x1.y + x1.z*x1.z + x1.w*x1.w;
#pragma unroll
    for (int o = 16; o > 0; o >>= 1) ss += __shfl_xor_sync(0xffffffffu, ss, o);
    const float scale = rsqrtf(ss * (1.0f / HD) + EPS);

    const float* nw = (slot < 8) ? qn_w : kn_w;
    float4 nw0 = *(const float4*)(nw + d0);
    float4 nw1 = *(const float4*)(nw + 128 + d0);
    float4 xn0, xn1;
    xn0.x = x0.x * scale * (1.0f + nw0.x); xn0.y = x0.y * scale * (1.0f + nw0.y);
    xn0.z = x0.z * scale * (1.0f + nw0.z); xn0.w = x0.w * scale * (1.0f + nw0.w);
    xn1.x = x1.x * scale * (1.0f + nw1.x); xn1.y = x1.y * scale * (1.0f + nw1.y);
    xn1.z = x1.z * scale * (1.0f + nw1.z); xn1.w = x1.w * scale * (1.0f + nw1.w);

    const size_t csi = ((size_t)b * S + s) * HD;
    float4 c0 = *(const float4*)(cosp + csi + d0);
    float4 c1 = *(const float4*)(cosp + csi + 128 + d0);
    float4 s0 = *(const float4*)(sinp + csi + d0);
    float4 s1 = *(const float4*)(sinp + csi + 128 + d0);

    float4 o0, o1;   // rotate_half: d<128 pairs with -x[d+128]; d>=128 pairs with +x[d-128]
    o0.x = xn0.x * c0.x - xn1.x * s0.x;  o0.y = xn0.y * c0.y - xn1.y * s0.y;
    o0.z = xn0.z * c0.z - xn1.z * s0.z;  o0.w = xn0.w * c0.w - xn1.w * s0.w;
    o1.x = xn1.x * c1.x + xn0.x * s1.x;  o1.y = xn1.y * c1.y + xn0.y * s1.y;
    o1.z = xn1.z * c1.z + xn0.z * s1.z;  o1.w = xn1.w * c1.w + xn0.w * s1.w;

    __nv_bfloat16 h[4], l[4];
    if (slot < 8) {
        size_t o = (((size_t)b * H + slot) * S + s) * HD;
        split4(o0, h, l); st8(g_qh + o + d0, h); st8(g_ql + o + d0, l);
        split4(o1, h, l); st8(g_qh + o + 128 + d0, h); st8(g_ql + o + 128 + d0, l);
    } else {
        size_t o = (((size_t)b * HKV + (slot - 8)) * S + s) * HD;
        split4(o0, h, l); st8(g_kh + o + d0, h); st8(g_kl + o + d0, l);
        split4(o1, h, l); st8(g_kh + o + 128 + d0, h); st8(g_kl + o + 128 + d0, l);
    }
}

// ---------------- Flash attention v2 + poly softcap (biggest tiles first) ----------------
constexpr int FLASH2_SMEM = 196608;   // 64KB Q + 2*64KB stages

__global__ __launch_bounds__(128) void flash_mma()
{
    extern __shared__ char fsm[];
    const uint32_t sb0 = smem_to_u32(fsm);
    const uint32_t sQh = sb0, sQl = sb0 + 32768;

    const int qt = gridDim.x - 1 - blockIdx.x;   // largest causal blocks scheduled first
    const int h  = blockIdx.y;
    const int b  = blockIdx.z;
    const int q0 = qt * 64;
    const int hk = h >> 1;

    const int tid = threadIdx.x, warp = tid >> 5, lane = tid & 31;

    const __nv_bfloat16* Qhp = g_qh + (((size_t)b * H   + h ) * S + q0) * HD;
    const __nv_bfloat16* Qlp = g_ql + (((size_t)b * H   + h ) * S + q0) * HD;
    const __nv_bfloat16* Khp = g_kh + (((size_t)b * HKV + hk) * S) * HD;
    const __nv_bfloat16* Klp = g_kl + (((size_t)b * HKV + hk) * S) * HD;
    const __nv_bfloat16* Vhp = g_vh + (((size_t)b * HKV + hk) * S) * HD;
    const __nv_bfloat16* Vlp = g_vl + (((size_t)b * HKV + hk) * S) * HD;

    for (int u = tid; u < 2048; u += 128) {
        int row = u >> 5, c = u & 31;
        uint32_t off = (uint32_t)row * 512 + (((uint32_t)c * 16) ^ (((uint32_t)row & 7) << 4));
        cp16(sQh + off, Qhp + (size_t)row * HD + c * 8);
        cp16(sQl + off, Qlp + (size_t)row * HD + c * 8);
    }
    CP_COMMIT();

    const int ntiles = 2 * (qt + 1);

#pragma unroll 1
    for (int pt = 0; pt < 2; pt++) {
        uint32_t sB = sb0 + 65536 + pt * 65536;
        int j0 = pt * 32;
        for (int u = tid; u < 1024; u += 128) {
            int row = u >> 5, c = u & 31;
            uint32_t off = (uint32_t)row * 512 + (((uint32_t)c * 16) ^ (((uint32_t)row & 7) << 4));
            size_t g = (size_t)(j0 + row) * HD + c * 8;
            cp16(sB + off,         Khp + g);
            cp16(sB + 16384 + off, Klp + g);
            cp16(sB + 32768 + off, Vhp + g);
            cp16(sB + 49152 + off, Vlp + g);
        }
        CP_COMMIT();
    }

    float acc[32][4];
#pragma unroll
    for (int i = 0; i < 32; i++) { acc[i][0]=0.f; acc[i][1]=0.f; acc[i][2]=0.f; acc[i][3]=0.f; }
    float mrow0 = -1e30f, mrow1 = -1e30f, lrow0 = 0.f, lrow1 = 0.f;

    const int rA = q0 + warp * 16 + (lane >> 2);

    const int arow = warp * 16 + (lane & 15);
    const uint32_t aswz = ((uint32_t)(arow & 7)) << 4;
    const uint32_t asel = (uint32_t)(lane >> 4) * 16;
    const int brow = (lane & 7) + ((lane >> 4) & 1) * 8;
    const uint32_t bswz = ((uint32_t)(brow & 7)) << 4;
    const uint32_t bsel = (uint32_t)((lane >> 3) & 1) * 16;
    const int vlanerow = (lane & 7) + ((lane >> 3) & 1) * 8;
    const uint32_t vdsel = (uint32_t)((lane >> 4) & 1) * 16;

    for (int t = 0; t < ntiles; t++) {
        if (t + 1 < ntiles) cp_wait<1>(); else cp_wait<0>();
        __syncthreads();
        const uint32_t sK = sb0 + 65536 + (t & 1) * 65536;
        const uint32_t sV = sK + 32768;

        float sc[4][4];
#pragma unroll
        for (int i = 0; i < 4; i++) { sc[i][0]=0.f; sc[i][1]=0.f; sc[i][2]=0.f; sc[i][3]=0.f; }

#pragma unroll 4
        for (int kc = 0; kc < 16; kc++) {
            uint32_t kb_a = ((uint32_t)(kc * 32) + asel) ^ aswz;
            uint32_t aq[4], al[4];
            ldm_x4(aq, sQh + (uint32_t)arow * 512 + kb_a);
            ldm_x4(al, sQl + (uint32_t)arow * 512 + kb_a);
            uint32_t kb_b = ((uint32_t)(kc * 32) + bsel) ^ bswz;
            uint32_t bh0[4], bh1[4], bl0[4], bl1[4];
            ldm_x4(bh0, sK + (uint32_t)brow * 512 + kb_b);
            ldm_x4(bh1, sK + (uint32_t)(brow + 16) * 512 + kb_b);
            ldm_x4(bl0, sK + 16384 + (uint32_t)brow * 512 + kb_b);
            ldm_x4(bl1, sK + 16384 + (uint32_t)(brow + 16) * 512 + kb_b);

            mma_bf16(sc[0], aq, bh0[0], bh0[1]); mma_bf16(sc[0], al, bh0[0], bh0[1]); mma_bf16(sc[0], aq, bl0[0], bl0[1]);
            mma_bf16(sc[1], aq, bh0[2], bh0[3]); mma_bf16(sc[1], al, bh0[2], bh0[3]); mma_bf16(sc[1], aq, bl0[2], bl0[3]);
            mma_bf16(sc[2], aq, bh1[0], bh1[1]); mma_bf16(sc[2], al, bh1[0], bh1[1]); mma_bf16(sc[2], aq, bl1[0], bl1[1]);
            mma_bf16(sc[3], aq, bh1[2], bh1[3]); mma_bf16(sc[3], al, bh1[2], bh1[3]); mma_bf16(sc[3], aq, bl1[2], bl1[3]);
        }

        const int j0 = t * 32;
        float mn0 = mrow0, mn1 = mrow1;
#pragma unroll
        for (int nf = 0; nf < 4; nf++) {
            const int cb = j0 + nf * 8 + (lane & 3) * 2;
#pragma unroll
            for (int e = 0; e < 4; e++) {
                float w = sc[nf][e] * SCALING;
                const float tt = w * (1.0f / SOFTCAP);
                w = w * (1.0f - 0.33333333f * tt * tt);   // C*tanh(w/C), |tt|<=0.004
                const int col = cb + (e & 1);
                const int rowg = (e < 2) ? rA : (rA + 8);
                if (col > rowg) w = NEGBIG;
                sc[nf][e] = w;
                if (e < 2) mn0 = fmaxf(mn0, w); else mn1 = fmaxf(mn1, w);
            }
        }
        mn0 = fmaxf(mn0, __shfl_xor_sync(0xffffffffu, mn0, 1));
        mn0 = fmaxf(mn0, __shfl_xor_sync(0xffffffffu, mn0, 2));
        mn1 = fmaxf(mn1, __shfl_xor_sync(0xffffffffu, mn1, 1));
        mn1 = fmaxf(mn1, __shfl_xor_sync(0xffffffffu, mn1, 2));
        const float corr0 = __expf(mrow0 - mn0);
        const float corr1 = __expf(mrow1 - mn1);
        mrow0 = mn0; mrow1 = mn1;

        float ps0 = 0.f, ps1 = 0.f;
        uint32_t aphi[2][4], aplo[2][4];
#pragma unroll
        for (int f = 0; f < 2; f++) {
#pragma unroll
            for (int hf = 0; hf < 2; hf++) {
                const int nf = 2 * f + hf;
                float p00 = __expf(sc[nf][0] - mn0), p01 = __expf(sc[nf][1] - mn0);
                float p10 = __expf(sc[nf][2] - mn1), p11 = __expf(sc[nf][3] - mn1);
                ps0 += p00 + p01; ps1 += p10 + p11;
                float h00 = __bfloat162float(__float2bfloat16(p00));
                float h01 = __bfloat162float(__float2bfloat16(p01));
                float h10 = __bfloat162float(__float2bfloat16(p10));
                float h11 = __bfloat162float(__float2bfloat16(p11));
                aphi[f][hf * 2 + 0] = pack_bf16(h00, h01);
                aphi[f][hf * 2 + 1] = pack_bf16(h10, h11);
                aplo[f][hf * 2 + 0] = pack_bf16(p00 - h00, p01 - h01);
                aplo[f][hf * 2 + 1] = pack_bf16(p10 - h10, p11 - h11);
            }
        }
        ps0 += __shfl_xor_sync(0xffffffffu, ps0, 1);
        ps0 += __shfl_xor_sync(0xffffffffu, ps0, 2);
        ps1 += __shfl_xor_sync(0xffffffffu, ps1, 1);
        ps1 += __shfl_xor_sync(0xffffffffu, ps1, 2);
        lrow0 = lrow0 * corr0 + ps0;
        lrow1 = lrow1 * corr1 + ps1;

#pragma unroll
        for (int nf = 0; nf < 32; nf++) {
            acc[nf][0] *= corr0; acc[nf][1] *= corr0;
            acc[nf][2] *= corr1; acc[nf][3] *= corr1;
        }

#pragma unroll
        for (int kf = 0; kf < 2; kf++) {
            const int jrow = kf * 16 + vlanerow;
            const uint32_t vbase = sV + (uint32_t)jrow * 512;
            const uint32_t vswz = ((uint32_t)(jrow & 7)) << 4;
#pragma unroll
            for (int g16 = 0; g16 < 16; g16++) {
                uint32_t dby = ((uint32_t)(g16 * 32) + vdsel) ^ vswz;
                uint32_t vhf[4], vlf[4];
                ldm_x4_t(vhf, vbase + dby);
                ldm_x4_t(vlf, vbase + 16384 + dby);
                mma_bf16(acc[2 * g16],     aphi[kf], vhf[0], vhf[1]);
                mma_bf16(acc[2 * g16],     aplo[kf], vhf[0], vhf[1]);
                mma_bf16(acc[2 * g16],     aphi[kf], vlf[0], vlf[1]);
                mma_bf16(acc[2 * g16 + 1], aphi[kf], vhf[2], vhf[3]);
                mma_bf16(acc[2 * g16 + 1], aplo[kf], vhf[2], vhf[3]);
                mma_bf16(acc[2 * g16 + 1], aphi[kf], vlf[2], vlf[3]);
            }
        }

        __syncthreads();
        if (t + 2 < ntiles) {
            uint32_t sB = sb0 + 65536 + (t & 1) * 65536;
            int j0n = (t + 2) * 32;
            for (int u = tid; u < 1024; u += 128) {
                int row = u >> 5, c = u & 31;
                uint32_t off = (uint32_t)row * 512 + (((uint32_t)c * 16) ^ (((uint32_t)row & 7) << 4));
                size_t g = (size_t)(j0n + row) * HD + c * 8;
                cp16(sB + off,         Khp + g);
                cp16(sB + 16384 + off, Klp + g);
                cp16(sB + 32768 + off, Vhp + g);
                cp16(sB + 49152 + off, Vlp + g);
            }
            CP_COMMIT();
        }
    }

    const float inv0 = 1.0f / lrow0;
    const float inv1 = 1.0f / lrow1;
    const size_t tokA = (size_t)b * S + q0 + warp * 16 + (lane >> 2);
    __nv_bfloat16* rowAh = g_ah + tokA * (size_t)K2 + h * HD;
    __nv_bfloat16* rowAl = g_al + tokA * (size_t)K2 + h * HD;
    __nv_bfloat16* rowBh = g_ah + (tokA + 8) * (size_t)K2 + h * HD;
    __nv_bfloat16* rowBl = g_al + (tokA + 8) * (size_t)K2 + h * HD;
#pragma unroll
    for (int nf = 0; nf < 32; nf++) {
        const int d = nf * 8 + (lane & 3) * 2;
        {
            float v0 = acc[nf][0] * inv0, v1 = acc[nf][1] * inv0;
            float h0 = __bfloat162float(__float2bfloat16(v0));
            float h1 = __bfloat162float(__float2bfloat16(v1));
            *(__nv_bfloat162*)(rowAh + d) = __floats2bfloat162_rn(h0, h1);
            *(__nv_bfloat162*)(rowAl + d) = __floats2bfloat162_rn(v0 - h0, v1 - h1);
        }
        {
            float v0 = acc[nf][2] * inv1, v1 = acc[nf][3] * inv1;
            float h0 = __bfloat162float(__float2bfloat16(v0));
            float h1 = __bfloat162float(__float2bfloat16(v1));
            *(__nv_bfloat162*)(rowBh + d) = __floats2bfloat162_rn(h0, h1);
            *(__nv_bfloat162*)(rowBl + d) = __floats2bfloat162_rn(v0 - h0, v1 - h1);
        }
    }
}

// ---------------- Host launch ----------------
extern "C" void kernel_launch(void* const* d_in, const int* in_sizes, int n_in,
                              void* d_out, int out_size)
{
    const float* x    = (const float*)d_in[0];
    const float* cosp = (const float*)d_in[1];
    const float* sinp = (const float*)d_in[2];
    const float* q_w  = (const float*)d_in[4];
    const float* k_w  = (const float*)d_in[5];
    const float* v_w  = (const float*)d_in[6];
    const float* o_w  = (const float*)d_in[7];
    const float* qn_w = (const float*)d_in[8];
    const float* kn_w = (const float*)d_in[9];
    float* out = (float*)d_out;

    void *p_qkv, *p_xh, *p_xl, *p_wh, *p_wl, *p_ah, *p_al, *p_owh, *p_owl;
    cudaGetSymbolAddress(&p_qkv, g_qkv);
    cudaGetSymbolAddress(&p_xh,  g_xh);
    cudaGetSymbolAddress(&p_xl,  g_xl);
    cudaGetSymbolAddress(&p_wh,  g_wh);
    cudaGetSymbolAddress(&p_wl,  g_wl);
    cudaGetSymbolAddress(&p_ah,  g_ah);
    cudaGetSymbolAddress(&p_al,  g_al);
    cudaGetSymbolAddress(&p_owh, g_owh);
    cudaGetSymbolAddress(&p_owl, g_owl);
    float* qkv = (float*)p_qkv;
    __nv_bfloat16* xh  = (__nv_bfloat16*)p_xh;
    __nv_bfloat16* xl  = (__nv_bfloat16*)p_xl;
    __nv_bfloat16* wh  = (__nv_bfloat16*)p_wh;
    __nv_bfloat16* wl  = (__nv_bfloat16*)p_wl;
    __nv_bfloat16* ah  = (__nv_bfloat16*)p_ah;
    __nv_bfloat16* al  = (__nv_bfloat16*)p_al;
    __nv_bfloat16* owh = (__nv_bfloat16*)p_owh;
    __nv_bfloat16* owl = (__nv_bfloat16*)p_owl;

    cudaFuncSetAttribute(gemm_bf16x3, cudaFuncAttributeMaxDynamicSharedMemorySize, GEMM_SMEM);
    cudaFuncSetAttribute(flash_mma,   cudaFuncAttributeMaxDynamicSharedMemorySize, FLASH2_SMEM);

    // 1) split-convert x and QKV weights
    {
        long tot = (long)NTOK * (K1 / 4);
        conv_split<<<(unsigned)((tot + 255) / 256), 256>>>(x, xh, xl, tot);
        long totw = (long)QKV_COLS * (K1 / 4);
        conv_split_qkv<<<(unsigned)((totw + 255) / 256), 256>>>(q_w, k_w, v_w, wh, wl);
    }
    // 2) QKV projection (3-term HMMA, 2 CTAs/SM)
    gemm_bf16x3<<<dim3(QKV_COLS / 128, NTOK / 128), 256, GEMM_SMEM>>>(xh, xl, wh, wl, qkv, K1, QKV_COLS);

    // 3) RMSNorm + RoPE (warp-per-row) + bf16 hi/lo split
    norm_rope_kernel<<<dim3(NTOK, 2), 256>>>(cosp, sinp, qn_w, kn_w);

    // 4) Flash attention v2 (writes g_ah/g_al)
    flash_mma<<<dim3(S / 64, H, B), 128, FLASH2_SMEM>>>();

    // 5) split-convert O weights
    {
        long totw = (long)D * (K2 / 4);
        conv_split<<<(unsigned)((totw + 255) / 256), 256>>>(o_w, owh, owl, totw);
    }
    // 6) O projection
    gemm_bf16x3<<<dim3(D / 128, NTOK / 128), 256, GEMM_SMEM>>>(ah, al, owh, owl, out, K2, D);
}